// round 1
// baseline (speedup 1.0000x reference)
#include <cuda_runtime.h>
#include <cuda_bf16.h>
#include <math.h>

// Problem constants
#define L_DIM 1024
#define B_DIM 8
#define E_DIM 1024
#define H_DIM 16
#define HD    64
#define M_ROWS (L_DIM * B_DIM)      // 8192
#define QKV_N  (3 * E_DIM)          // 3072
#define ROW3E  (3 * E_DIM)          // row stride of qkv buffer in floats

// Scratch (allocation-free rule: __device__ globals)
__device__ float g_qkv[(size_t)M_ROWS * QKV_N];   // ~100.7 MB
__device__ float g_attn[(size_t)M_ROWS * E_DIM];  // ~33.6 MB

// ---------------------------------------------------------------------------
// SGEMM: C[M,N] = A[M,K] @ W[N,K]^T + bias[N]
// Tile 128x128x8, 256 threads, 8x8 per thread.
// Assumes M%128==0, N%128==0, K%8==0 (true for all uses here).
// ---------------------------------------------------------------------------
__global__ void __launch_bounds__(256) sgemm_bias_kernel(
    const float* __restrict__ A, const float* __restrict__ W,
    const float* __restrict__ bias, float* __restrict__ C,
    int M, int N, int K)
{
    __shared__ float As[8][128];
    __shared__ float Ws[8][128];

    const int tid = threadIdx.x;
    const int tx = tid & 15;          // 0..15 -> N direction
    const int ty = tid >> 4;          // 0..15 -> M direction
    const int rowBase = blockIdx.y * 128;
    const int colBase = blockIdx.x * 128;

    // load mapping: each thread fetches one float4 of A and of W per k-tile
    const int lrow = tid >> 1;        // 0..127
    const int lk   = (tid & 1) * 4;   // 0 or 4
    const float* Aptr = A + (size_t)(rowBase + lrow) * K + lk;
    const float* Wptr = W + (size_t)(colBase + lrow) * K + lk;

    float acc[8][8];
#pragma unroll
    for (int i = 0; i < 8; i++)
#pragma unroll
        for (int j = 0; j < 8; j++) acc[i][j] = 0.f;

    for (int k0 = 0; k0 < K; k0 += 8) {
        float4 av = *(const float4*)(Aptr + k0);
        float4 wv = *(const float4*)(Wptr + k0);
        __syncthreads();  // previous compute done before overwrite
        As[lk + 0][lrow] = av.x; As[lk + 1][lrow] = av.y;
        As[lk + 2][lrow] = av.z; As[lk + 3][lrow] = av.w;
        Ws[lk + 0][lrow] = wv.x; Ws[lk + 1][lrow] = wv.y;
        Ws[lk + 2][lrow] = wv.z; Ws[lk + 3][lrow] = wv.w;
        __syncthreads();

#pragma unroll
        for (int k = 0; k < 8; k++) {
            float4 a0 = *(const float4*)&As[k][ty * 8];
            float4 a1 = *(const float4*)&As[k][ty * 8 + 4];
            float4 b0 = *(const float4*)&Ws[k][tx * 8];
            float4 b1 = *(const float4*)&Ws[k][tx * 8 + 4];
            float a[8] = {a0.x, a0.y, a0.z, a0.w, a1.x, a1.y, a1.z, a1.w};
            float b[8] = {b0.x, b0.y, b0.z, b0.w, b1.x, b1.y, b1.z, b1.w};
#pragma unroll
            for (int i = 0; i < 8; i++)
#pragma unroll
                for (int j = 0; j < 8; j++)
                    acc[i][j] = fmaf(a[i], b[j], acc[i][j]);
        }
    }

    // epilogue: + bias, store (float4)
    float bv[8];
#pragma unroll
    for (int j = 0; j < 8; j++) bv[j] = bias[colBase + tx * 8 + j];

#pragma unroll
    for (int i = 0; i < 8; i++) {
        float* crow = C + (size_t)(rowBase + ty * 8 + i) * N + colBase + tx * 8;
        float4 o0, o1;
        o0.x = acc[i][0] + bv[0]; o0.y = acc[i][1] + bv[1];
        o0.z = acc[i][2] + bv[2]; o0.w = acc[i][3] + bv[3];
        o1.x = acc[i][4] + bv[4]; o1.y = acc[i][5] + bv[5];
        o1.z = acc[i][6] + bv[6]; o1.w = acc[i][7] + bv[7];
        *(float4*)(crow)     = o0;
        *(float4*)(crow + 4) = o1;
    }
}

// ---------------------------------------------------------------------------
// Flash attention, fp32. One block = one (b,h) pair x 64 query rows.
// qkv layout: [L, B, 3E] row-major; per (b,h): q at col h*64, k at E + h*64,
// v at 2E + h*64. Row stride between consecutive l (fixed b) = B*3E = 24576.
// Output: g_attn[(l*B + b)*E + h*64 + d]
// ---------------------------------------------------------------------------
__global__ void __launch_bounds__(256) flash_attn_kernel(
    const float* __restrict__ qkv, float* __restrict__ outp)
{
    extern __shared__ float sm[];
    float* Qst = sm;                 // [64][65] transposed: Qst[d*65 + m]
    float* Kst = Qst + 64 * 65;      // [64][65] transposed: Kst[d*65 + n]
    float* Vs  = Kst + 64 * 65;      // [64][64] natural:    Vs[n*64 + d]
    float* Ps  = Vs + 64 * 64;       // [64][64] natural:    Ps[m*64 + n]

    const int tid = threadIdx.x;
    const int tx = tid & 15;         // key/feature dim groups
    const int ty = tid >> 4;         // query row groups
    const int bh = blockIdx.y;
    const int b  = bh >> 4;
    const int h  = bh & 15;
    const int q0 = blockIdx.x * 64;

    const int ldrow = tid >> 6;      // 0..3
    const int ldcol = tid & 63;      // 0..63

    const size_t rstride = (size_t)B_DIM * ROW3E;  // 24576
    const float* qbase = qkv + (size_t)(q0 * B_DIM + b) * ROW3E + h * HD;

    // Load Q (scaled by 1/sqrt(hd) = 0.125), transposed
#pragma unroll
    for (int r0 = 0; r0 < 64; r0 += 4) {
        int r = r0 + ldrow;
        Qst[ldcol * 65 + r] = qbase[(size_t)r * rstride + ldcol] * 0.125f;
    }

    float o[4][4];
    float mi[4], li[4];
#pragma unroll
    for (int i = 0; i < 4; i++) {
        mi[i] = -1e30f; li[i] = 0.f;
#pragma unroll
        for (int j = 0; j < 4; j++) o[i][j] = 0.f;
    }
    __syncthreads();

    for (int kt = 0; kt < 16; kt++) {
        const float* kbase = qkv + (size_t)((kt * 64) * B_DIM + b) * ROW3E + E_DIM + h * HD;
        const float* vbase = kbase + E_DIM;

        // load K (transposed) and V (natural)
#pragma unroll
        for (int r0 = 0; r0 < 64; r0 += 4) {
            int r = r0 + ldrow;
            float kv = kbase[(size_t)r * rstride + ldcol];
            float vv = vbase[(size_t)r * rstride + ldcol];
            Kst[ldcol * 65 + r] = kv;
            Vs[r * 64 + ldcol]  = vv;
        }
        __syncthreads();

        // S = Q K^T  (4x4 per thread)
        float s[4][4];
#pragma unroll
        for (int i = 0; i < 4; i++)
#pragma unroll
            for (int j = 0; j < 4; j++) s[i][j] = 0.f;

#pragma unroll 8
        for (int d = 0; d < 64; d++) {
            float a[4], bb[4];
#pragma unroll
            for (int i = 0; i < 4; i++) a[i]  = Qst[d * 65 + ty * 4 + i];
#pragma unroll
            for (int j = 0; j < 4; j++) bb[j] = Kst[d * 65 + tx * 4 + j];
#pragma unroll
            for (int i = 0; i < 4; i++)
#pragma unroll
                for (int j = 0; j < 4; j++)
                    s[i][j] = fmaf(a[i], bb[j], s[i][j]);
        }

        // online softmax (row groups are 16 consecutive lanes -> shfl width 16)
#pragma unroll
        for (int i = 0; i < 4; i++) {
            float rm = fmaxf(fmaxf(s[i][0], s[i][1]), fmaxf(s[i][2], s[i][3]));
#pragma unroll
            for (int off = 8; off > 0; off >>= 1)
                rm = fmaxf(rm, __shfl_xor_sync(0xffffffffu, rm, off));
            float mn = fmaxf(mi[i], rm);
            float alpha = __expf(mi[i] - mn);
            float rs = 0.f;
#pragma unroll
            for (int j = 0; j < 4; j++) {
                float p = __expf(s[i][j] - mn);
                s[i][j] = p;
                rs += p;
            }
#pragma unroll
            for (int off = 8; off > 0; off >>= 1)
                rs += __shfl_xor_sync(0xffffffffu, rs, off);
            li[i] = li[i] * alpha + rs;
            mi[i] = mn;
#pragma unroll
            for (int j = 0; j < 4; j++) o[i][j] *= alpha;
        }

        // publish P
#pragma unroll
        for (int i = 0; i < 4; i++)
#pragma unroll
            for (int j = 0; j < 4; j++)
                Ps[(ty * 4 + i) * 64 + tx * 4 + j] = s[i][j];
        __syncthreads();

        // O += P @ V
#pragma unroll 8
        for (int n = 0; n < 64; n++) {
            float a[4], bb[4];
#pragma unroll
            for (int i = 0; i < 4; i++) a[i]  = Ps[(ty * 4 + i) * 64 + n];
#pragma unroll
            for (int j = 0; j < 4; j++) bb[j] = Vs[n * 64 + tx * 4 + j];
#pragma unroll
            for (int i = 0; i < 4; i++)
#pragma unroll
                for (int j = 0; j < 4; j++)
                    o[i][j] = fmaf(a[i], bb[j], o[i][j]);
        }
        __syncthreads();
    }

    // epilogue: normalize and write to [L,B,E] layout at head offset
#pragma unroll
    for (int i = 0; i < 4; i++) {
        int m = ty * 4 + i;
        float inv = 1.0f / li[i];
        float* orow = outp + (size_t)((q0 + m) * B_DIM + b) * E_DIM + h * HD + tx * 4;
        float4 v;
        v.x = o[i][0] * inv; v.y = o[i][1] * inv;
        v.z = o[i][2] * inv; v.w = o[i][3] * inv;
        *(float4*)orow = v;
    }
}

// ---------------------------------------------------------------------------
// Launch
// ---------------------------------------------------------------------------
extern "C" void kernel_launch(void* const* d_in, const int* in_sizes, int n_in,
                              void* d_out, int out_size)
{
    const float* x     = (const float*)d_in[0];
    const float* wqkv  = (const float*)d_in[1];
    const float* bqkv  = (const float*)d_in[2];
    const float* wout  = (const float*)d_in[3];
    const float* bout  = (const float*)d_in[4];
    float* out = (float*)d_out;

    float* qkv  = nullptr;
    float* attn = nullptr;
    cudaGetSymbolAddress((void**)&qkv,  g_qkv);
    cudaGetSymbolAddress((void**)&attn, g_attn);

    // Flash attention needs 66 KB dynamic smem
    static const size_t FLASH_SMEM = (size_t)(64 * 65 * 2 + 64 * 64 * 2) * sizeof(float);
    cudaFuncSetAttribute(flash_attn_kernel,
                         cudaFuncAttributeMaxDynamicSharedMemorySize,
                         (int)FLASH_SMEM);

    // 1) QKV projection: [8192,1024] @ [3072,1024]^T + bias -> [8192,3072]
    {
        dim3 grid(QKV_N / 128, M_ROWS / 128);
        sgemm_bias_kernel<<<grid, 256>>>(x, wqkv, bqkv, qkv, M_ROWS, QKV_N, E_DIM);
    }

    // 2) Attention: 128 (b,h) pairs x 16 query tiles
    {
        dim3 grid(L_DIM / 64, B_DIM * H_DIM);
        flash_attn_kernel<<<grid, 256, FLASH_SMEM>>>(qkv, attn);
    }

    // 3) Output projection: [8192,1024] @ [1024,1024]^T + bias -> d_out
    {
        dim3 grid(E_DIM / 128, M_ROWS / 128);
        sgemm_bias_kernel<<<grid, 256>>>(attn, wout, bout, out, M_ROWS, E_DIM, E_DIM);
    }
}

// round 2
// speedup vs baseline: 2.9079x; 2.9079x over previous
#include <cuda_runtime.h>
#include <cuda_bf16.h>
#include <math.h>

// Problem constants
#define L_DIM 1024
#define B_DIM 8
#define E_DIM 1024
#define H_DIM 16
#define HD    64
#define M_ROWS (L_DIM * B_DIM)      // 8192
#define QKV_N  (3 * E_DIM)          // 3072
#define ROW3E  (3 * E_DIM)

// Scratch (allocation-free rule: __device__ globals)
__device__ float g_qkv[(size_t)M_ROWS * QKV_N];   // ~100.7 MB
__device__ float g_attn[(size_t)M_ROWS * E_DIM];  // ~33.6 MB

__device__ __forceinline__ float to_tf32(float x) {
    float y;
    asm("cvt.rna.tf32.f32 %0, %1;" : "=f"(y) : "f"(x));
    return y;
}

__device__ __forceinline__ void mma_tf32(float* c, const float* a, const float* b) {
    asm volatile(
        "mma.sync.aligned.m16n8k8.row.col.f32.tf32.tf32.f32 "
        "{%0,%1,%2,%3}, {%4,%5,%6,%7}, {%8,%9}, {%0,%1,%2,%3};\n"
        : "+f"(c[0]), "+f"(c[1]), "+f"(c[2]), "+f"(c[3])
        : "r"(__float_as_uint(a[0])), "r"(__float_as_uint(a[1])),
          "r"(__float_as_uint(a[2])), "r"(__float_as_uint(a[3])),
          "r"(__float_as_uint(b[0])), "r"(__float_as_uint(b[1])));
}

// ---------------------------------------------------------------------------
// TF32 GEMM: C[M,N] = A[M,K] @ W[N,K]^T + bias[N]
// Block tile 128x128, K-tile 32. 256 threads = 8 warps, warp tile 64x32.
// Smem stride 36 -> conflict-free fragment loads.
// ---------------------------------------------------------------------------
#define GS 36
__global__ void __launch_bounds__(256) gemm_tf32_kernel(
    const float* __restrict__ A, const float* __restrict__ W,
    const float* __restrict__ bias, float* __restrict__ C,
    int M, int N, int K)
{
    __shared__ float As[128 * GS];
    __shared__ float Ws[128 * GS];

    const int tid  = threadIdx.x;
    const int wid  = tid >> 5;
    const int lane = tid & 31;
    const int g    = lane >> 2;   // 0..7
    const int tg   = lane & 3;    // 0..3
    const int wm   = (wid >> 2) * 64;  // 0 / 64
    const int wn   = (wid & 3) * 32;   // 0..96
    const int rowBase = blockIdx.y * 128;
    const int colBase = blockIdx.x * 128;

    float c[4][4][4];
#pragma unroll
    for (int mi = 0; mi < 4; mi++)
#pragma unroll
        for (int nj = 0; nj < 4; nj++)
#pragma unroll
            for (int r = 0; r < 4; r++) c[mi][nj][r] = 0.f;

    for (int k0 = 0; k0 < K; k0 += 32) {
        __syncthreads();
        // stage A and W tiles (128x32 each) with tf32 rounding
#pragma unroll
        for (int p = 0; p < 4; p++) {
            int f4  = tid + p * 256;
            int r   = f4 >> 3;
            int c4  = (f4 & 7) * 4;
            float4 av = *(const float4*)(A + (size_t)(rowBase + r) * K + k0 + c4);
            float4 wv = *(const float4*)(W + (size_t)(colBase + r) * K + k0 + c4);
            av.x = to_tf32(av.x); av.y = to_tf32(av.y);
            av.z = to_tf32(av.z); av.w = to_tf32(av.w);
            wv.x = to_tf32(wv.x); wv.y = to_tf32(wv.y);
            wv.z = to_tf32(wv.z); wv.w = to_tf32(wv.w);
            *(float4*)&As[r * GS + c4] = av;
            *(float4*)&Ws[r * GS + c4] = wv;
        }
        __syncthreads();

#pragma unroll
        for (int ks = 0; ks < 4; ks++) {
            const int kk = ks * 8;
            float a[4][4], b[4][2];
#pragma unroll
            for (int mi = 0; mi < 4; mi++) {
                int r0 = wm + mi * 16 + g;
                a[mi][0] = As[(r0    ) * GS + kk + tg];
                a[mi][1] = As[(r0 + 8) * GS + kk + tg];
                a[mi][2] = As[(r0    ) * GS + kk + tg + 4];
                a[mi][3] = As[(r0 + 8) * GS + kk + tg + 4];
            }
#pragma unroll
            for (int nj = 0; nj < 4; nj++) {
                int n0 = wn + nj * 8 + g;
                b[nj][0] = Ws[n0 * GS + kk + tg];
                b[nj][1] = Ws[n0 * GS + kk + tg + 4];
            }
#pragma unroll
            for (int mi = 0; mi < 4; mi++)
#pragma unroll
                for (int nj = 0; nj < 4; nj++)
                    mma_tf32(c[mi][nj], a[mi], b[nj]);
        }
    }

    // epilogue: + bias
#pragma unroll
    for (int mi = 0; mi < 4; mi++) {
#pragma unroll
        for (int nj = 0; nj < 4; nj++) {
            int row0 = rowBase + wm + mi * 16 + g;
            int col  = colBase + wn + nj * 8 + tg * 2;
            float b0 = bias[col], b1 = bias[col + 1];
            float2 v0 = make_float2(c[mi][nj][0] + b0, c[mi][nj][1] + b1);
            float2 v1 = make_float2(c[mi][nj][2] + b0, c[mi][nj][3] + b1);
            *(float2*)(C + (size_t)row0 * N + col)       = v0;
            *(float2*)(C + (size_t)(row0 + 8) * N + col) = v1;
        }
    }
}

// ---------------------------------------------------------------------------
// TF32 flash attention. One block = (b,h) x 128 query rows, 256 thr (8 warps).
// Each warp owns 16 full S rows -> row softmax stays in-warp (shfl over 4 lanes).
// P slab is warp-private in smem (no block sync around it).
// smem: Ks[64][68], Vs[64][68], Ps[128][68] (Ps doubles as Q staging).
// ---------------------------------------------------------------------------
#define FS 68
__global__ void __launch_bounds__(256) flash_tf32_kernel(
    const float* __restrict__ qkv, float* __restrict__ outp)
{
    extern __shared__ float sm[];
    float* Ks = sm;                  // 64*68
    float* Vs = Ks + 64 * FS;        // 64*68
    float* Ps = Vs + 64 * FS;        // 128*68 (Q staging, then P)

    const int tid  = threadIdx.x;
    const int wid  = tid >> 5;
    const int lane = tid & 31;
    const int g    = lane >> 2;
    const int tg   = lane & 3;
    const int wrow = wid * 16;

    const int bh = blockIdx.y;
    const int b  = bh >> 4;
    const int h  = bh & 15;
    const int q0 = blockIdx.x * 128;

    const size_t rstride = (size_t)B_DIM * ROW3E;  // 24576

    // ---- stage Q (scaled, tf32) into Ps ----
    {
        const float* qbase = qkv + (size_t)(q0 * B_DIM + b) * ROW3E + h * HD;
#pragma unroll
        for (int p = 0; p < 8; p++) {
            int f4 = tid + p * 256;
            int r  = f4 >> 4;
            int c4 = (f4 & 15) * 4;
            float4 v = *(const float4*)(qbase + (size_t)r * rstride + c4);
            v.x = to_tf32(v.x * 0.125f); v.y = to_tf32(v.y * 0.125f);
            v.z = to_tf32(v.z * 0.125f); v.w = to_tf32(v.w * 0.125f);
            *(float4*)&Ps[r * FS + c4] = v;
        }
    }
    __syncthreads();

    // ---- load Q fragments into registers (held for whole kv loop) ----
    float qa[8][4];
#pragma unroll
    for (int ks = 0; ks < 8; ks++) {
        int r0 = wrow + g;
        int kk = ks * 8;
        qa[ks][0] = Ps[(r0    ) * FS + kk + tg];
        qa[ks][1] = Ps[(r0 + 8) * FS + kk + tg];
        qa[ks][2] = Ps[(r0    ) * FS + kk + tg + 4];
        qa[ks][3] = Ps[(r0 + 8) * FS + kk + tg + 4];
    }

    float o[8][4];
#pragma unroll
    for (int nj = 0; nj < 8; nj++)
#pragma unroll
        for (int r = 0; r < 4; r++) o[nj][r] = 0.f;
    float m0 = -1e30f, m1 = -1e30f, l0 = 0.f, l1 = 0.f;

    for (int kt = 0; kt < 16; kt++) {
        __syncthreads();   // prior iter's Vs/Ks reads done
        // ---- stage K and V tiles (64x64) ----
        {
            const float* kbase = qkv + (size_t)((kt * 64) * B_DIM + b) * ROW3E + E_DIM + h * HD;
            const float* vbase = kbase + E_DIM;
#pragma unroll
            for (int p = 0; p < 4; p++) {
                int f4 = tid + p * 256;
                int r  = f4 >> 4;
                int c4 = (f4 & 15) * 4;
                float4 kv = *(const float4*)(kbase + (size_t)r * rstride + c4);
                float4 vv = *(const float4*)(vbase + (size_t)r * rstride + c4);
                kv.x = to_tf32(kv.x); kv.y = to_tf32(kv.y);
                kv.z = to_tf32(kv.z); kv.w = to_tf32(kv.w);
                vv.x = to_tf32(vv.x); vv.y = to_tf32(vv.y);
                vv.z = to_tf32(vv.z); vv.w = to_tf32(vv.w);
                *(float4*)&Ks[r * FS + c4] = kv;
                *(float4*)&Vs[r * FS + c4] = vv;
            }
        }
        __syncthreads();

        // ---- S = Q K^T : s[nj] covers cols nj*8..+8 of this warp's 16 rows ----
        float s[8][4];
#pragma unroll
        for (int nj = 0; nj < 8; nj++)
#pragma unroll
            for (int r = 0; r < 4; r++) s[nj][r] = 0.f;

#pragma unroll
        for (int ks = 0; ks < 8; ks++) {
            const int kk = ks * 8;
            float kb[8][2];
#pragma unroll
            for (int nj = 0; nj < 8; nj++) {
                int tok = nj * 8 + g;
                kb[nj][0] = Ks[tok * FS + kk + tg];
                kb[nj][1] = Ks[tok * FS + kk + tg + 4];
            }
#pragma unroll
            for (int nj = 0; nj < 8; nj++)
                mma_tf32(s[nj], qa[ks], kb[nj]);
        }

        // ---- online softmax on fragments (rows g and g+8) ----
        float rmax0 = -1e30f, rmax1 = -1e30f;
#pragma unroll
        for (int nj = 0; nj < 8; nj++) {
            rmax0 = fmaxf(rmax0, fmaxf(s[nj][0], s[nj][1]));
            rmax1 = fmaxf(rmax1, fmaxf(s[nj][2], s[nj][3]));
        }
        rmax0 = fmaxf(rmax0, __shfl_xor_sync(0xffffffffu, rmax0, 1));
        rmax0 = fmaxf(rmax0, __shfl_xor_sync(0xffffffffu, rmax0, 2));
        rmax1 = fmaxf(rmax1, __shfl_xor_sync(0xffffffffu, rmax1, 1));
        rmax1 = fmaxf(rmax1, __shfl_xor_sync(0xffffffffu, rmax1, 2));

        float nm0 = fmaxf(m0, rmax0), nm1 = fmaxf(m1, rmax1);
        float al0 = __expf(m0 - nm0), al1 = __expf(m1 - nm1);
        float rs0 = 0.f, rs1 = 0.f;
#pragma unroll
        for (int nj = 0; nj < 8; nj++) {
            s[nj][0] = __expf(s[nj][0] - nm0);
            s[nj][1] = __expf(s[nj][1] - nm0);
            s[nj][2] = __expf(s[nj][2] - nm1);
            s[nj][3] = __expf(s[nj][3] - nm1);
            rs0 += s[nj][0] + s[nj][1];
            rs1 += s[nj][2] + s[nj][3];
        }
        rs0 += __shfl_xor_sync(0xffffffffu, rs0, 1);
        rs0 += __shfl_xor_sync(0xffffffffu, rs0, 2);
        rs1 += __shfl_xor_sync(0xffffffffu, rs1, 1);
        rs1 += __shfl_xor_sync(0xffffffffu, rs1, 2);
        l0 = l0 * al0 + rs0;  m0 = nm0;
        l1 = l1 * al1 + rs1;  m1 = nm1;

#pragma unroll
        for (int nj = 0; nj < 8; nj++) {
            o[nj][0] *= al0; o[nj][1] *= al0;
            o[nj][2] *= al1; o[nj][3] *= al1;
        }

        // ---- write P (tf32) to warp-private smem slab ----
#pragma unroll
        for (int nj = 0; nj < 8; nj++) {
            int col = nj * 8 + tg * 2;
            float2 p0 = make_float2(to_tf32(s[nj][0]), to_tf32(s[nj][1]));
            float2 p1 = make_float2(to_tf32(s[nj][2]), to_tf32(s[nj][3]));
            *(float2*)&Ps[(wrow + g    ) * FS + col] = p0;
            *(float2*)&Ps[(wrow + g + 8) * FS + col] = p1;
        }
        __syncwarp();

        // ---- O += P @ V ----
#pragma unroll
        for (int ks = 0; ks < 8; ks++) {
            const int kk = ks * 8;
            float pa[4];
            int r0 = wrow + g;
            pa[0] = Ps[(r0    ) * FS + kk + tg];
            pa[1] = Ps[(r0 + 8) * FS + kk + tg];
            pa[2] = Ps[(r0    ) * FS + kk + tg + 4];
            pa[3] = Ps[(r0 + 8) * FS + kk + tg + 4];
            float vb[8][2];
#pragma unroll
            for (int nj = 0; nj < 8; nj++) {
                int d = nj * 8 + g;
                vb[nj][0] = Vs[(kk + tg    ) * FS + d];
                vb[nj][1] = Vs[(kk + tg + 4) * FS + d];
            }
#pragma unroll
            for (int nj = 0; nj < 8; nj++)
                mma_tf32(o[nj], pa, vb[nj]);
        }
    }

    // ---- epilogue: normalize, write to [L,B,E] at head offset ----
    float inv0 = 1.0f / l0, inv1 = 1.0f / l1;
#pragma unroll
    for (int nj = 0; nj < 8; nj++) {
        int col = h * HD + nj * 8 + tg * 2;
        int r0 = q0 + wrow + g;
        float2 v0 = make_float2(o[nj][0] * inv0, o[nj][1] * inv0);
        float2 v1 = make_float2(o[nj][2] * inv1, o[nj][3] * inv1);
        *(float2*)(outp + (size_t)(r0 * B_DIM + b) * E_DIM + col)       = v0;
        *(float2*)(outp + (size_t)((r0 + 8) * B_DIM + b) * E_DIM + col) = v1;
    }
}

// ---------------------------------------------------------------------------
// Launch
// ---------------------------------------------------------------------------
extern "C" void kernel_launch(void* const* d_in, const int* in_sizes, int n_in,
                              void* d_out, int out_size)
{
    const float* x    = (const float*)d_in[0];
    const float* wqkv = (const float*)d_in[1];
    const float* bqkv = (const float*)d_in[2];
    const float* wout = (const float*)d_in[3];
    const float* bout = (const float*)d_in[4];
    float* out = (float*)d_out;

    float* qkv  = nullptr;
    float* attn = nullptr;
    cudaGetSymbolAddress((void**)&qkv,  g_qkv);
    cudaGetSymbolAddress((void**)&attn, g_attn);

    const size_t FLASH_SMEM = (size_t)(64 * FS * 2 + 128 * FS) * sizeof(float); // 69632
    cudaFuncSetAttribute(flash_tf32_kernel,
                         cudaFuncAttributeMaxDynamicSharedMemorySize,
                         (int)FLASH_SMEM);

    // 1) QKV projection: [8192,1024] @ [3072,1024]^T + bias
    {
        dim3 grid(QKV_N / 128, M_ROWS / 128);
        gemm_tf32_kernel<<<grid, 256>>>(x, wqkv, bqkv, qkv, M_ROWS, QKV_N, E_DIM);
    }

    // 2) Attention: 8 q-tiles x 128 (b,h) pairs
    {
        dim3 grid(L_DIM / 128, B_DIM * H_DIM);
        flash_tf32_kernel<<<grid, 256, FLASH_SMEM>>>(qkv, attn);
    }

    // 3) Output projection: [8192,1024] @ [1024,1024]^T + bias
    {
        dim3 grid(E_DIM / 128, M_ROWS / 128);
        gemm_tf32_kernel<<<grid, 256>>>(attn, wout, bout, out, M_ROWS, E_DIM, E_DIM);
    }
}